// round 1
// baseline (speedup 1.0000x reference)
#include <cuda_runtime.h>
#include <math.h>
#include <stdint.h>

#define NN 8192
#define NW 256          // bitmap words per row (8192 bits)
#define EMAX 262144
#define SLOPE 0.01f     // leaky_relu default

// ---------------- scratch (device globals; no allocation allowed) -----------
__device__ float g_xw  [NN*256];
__device__ float g_h1  [NN*128];
__device__ float g_h2  [NN*256];
__device__ float g_q   [NN*256];
__device__ float g_k   [NN*256];
__device__ float g_hatt[NN*256];
__device__ float g_h3  [NN*64];
__device__ float g_res [NN*64];
__device__ float g_z   [NN*64];
__device__ float g_dinv[NN];
__device__ int   g_deg [NN];
__device__ int   g_off [NN+1];
__device__ int   g_cur [NN];
__device__ int   g_src [EMAX];
__device__ float g_nrm [EMAX];
__device__ unsigned g_bm[NN*NW];       // dedup adjacency bitmap (8 MB)
__device__ float g_sb  [NN*128];       // per-row edge scores
__device__ float g_sall[256];
__device__ float g_pool[64];
__device__ int   g_is64;

// ---------------- utility ---------------------------------------------------
__global__ void k_zero() {
    int i = blockIdx.x * blockDim.x + threadIdx.x;
    if (i < NN*NW) g_bm[i] = 0u;
    if (i < NN) { g_deg[i] = 0; g_cur[i] = 0; }
}

// detect int64 vs int32 edge_index on device (no host readback allowed)
__global__ void k_detect(const long long* p, int E) {
    __shared__ int bad;
    if (threadIdx.x == 0) bad = 0;
    __syncthreads();
    int step = E / 256; if (step < 1) step = 1;
    for (int idx = threadIdx.x; idx < 256; idx += blockDim.x) {
        long long pos = (long long)idx * step;
        if (pos >= E) pos = E - 1;          // first E int64 slots are safe for both dtypes
        long long v = p[pos];
        if (v < 0 || v >= NN) bad = 1;
    }
    __syncthreads();
    if (threadIdx.x == 0) g_is64 = bad ? 0 : 1;
}

__device__ __forceinline__ void get_edge(const void* ei, int E, int e, int& r, int& c) {
    if (g_is64) {
        const long long* p = (const long long*)ei;
        r = (int)p[e] & (NN-1); c = (int)p[(long long)E + e] & (NN-1);
    } else {
        const int* p = (const int*)ei;
        r = p[e] & (NN-1); c = p[E + e] & (NN-1);
    }
}

// ---------------- graph preprocessing ---------------------------------------
__global__ void k_deg(const void* ei, int E) {
    int e = blockIdx.x * blockDim.x + threadIdx.x;
    if (e >= E) return;
    int r, c; get_edge(ei, E, e, r, c);
    atomicAdd(&g_deg[c], 1);
}

__global__ void k_dinv() {
    int i = blockIdx.x * blockDim.x + threadIdx.x;
    if (i < NN) g_dinv[i] = rsqrtf((float)(g_deg[i] + 1));  // +1 self loop
}

__global__ void k_scan() {   // exclusive scan of g_deg -> g_off, 1 block 1024 thr
    __shared__ int sh[1024];
    int t = threadIdx.x;
    int loc[8]; int s = 0;
    #pragma unroll
    for (int i = 0; i < 8; i++) { loc[i] = g_deg[t*8 + i]; s += loc[i]; }
    sh[t] = s; __syncthreads();
    for (int d = 1; d < 1024; d <<= 1) {
        int v = (t >= d) ? sh[t-d] : 0;
        __syncthreads();
        sh[t] += v;
        __syncthreads();
    }
    int excl = sh[t] - s;
    #pragma unroll
    for (int i = 0; i < 8; i++) { g_off[t*8 + i] = excl; excl += loc[i]; }
    if (t == 1023) g_off[NN] = excl;
}

__global__ void k_fill(const void* ei, int E) {
    int e = blockIdx.x * blockDim.x + threadIdx.x;
    if (e >= E) return;
    int r, c; get_edge(ei, E, e, r, c);
    int p = atomicAdd(&g_cur[c], 1);
    int idx = g_off[c] + p;
    g_src[idx] = r;
    g_nrm[idx] = g_dinv[r] * g_dinv[c];
}

__global__ void k_bmset(const void* ei, int E) {
    int e = blockIdx.x * blockDim.x + threadIdx.x;
    if (e >= E) return;
    int r, c; get_edge(ei, E, e, r, c);
    atomicOr(&g_bm[r*NW + (c >> 5)], 1u << (c & 31));
}

// ---------------- GEMM: C[M,Ncols] = A[M,K] @ W[K,Ncols] (+bias) ------------
// 64x64 tile, 256 threads, 4x4 per thread, BK=16
__global__ void k_gemm(const float* __restrict__ A, const float* __restrict__ W,
                       const float* __restrict__ bias, float* __restrict__ C,
                       int K, int Ncols) {
    __shared__ float As[64][17];
    __shared__ float Bs[16][64];
    int t  = threadIdx.x;
    int tx = t & 15, ty = t >> 4;
    int rowBase = blockIdx.y * 64;
    int colBase = blockIdx.x * 64;
    float acc[4][4] = {};
    for (int k0 = 0; k0 < K; k0 += 16) {
        #pragma unroll
        for (int i = 0; i < 4; i++) {
            int idx = t + i*256;
            int ar = idx >> 4, ak = idx & 15;
            As[ar][ak] = A[(rowBase + ar) * K + k0 + ak];
            int br = idx >> 6, bc = idx & 63;
            Bs[br][bc] = W[(k0 + br) * Ncols + colBase + bc];
        }
        __syncthreads();
        #pragma unroll
        for (int kk = 0; kk < 16; kk++) {
            float4 b4 = *(const float4*)&Bs[kk][tx*4];
            float b[4] = {b4.x, b4.y, b4.z, b4.w};
            float a[4];
            #pragma unroll
            for (int i = 0; i < 4; i++) a[i] = As[ty*4 + i][kk];
            #pragma unroll
            for (int i = 0; i < 4; i++)
                #pragma unroll
                for (int j = 0; j < 4; j++)
                    acc[i][j] = fmaf(a[i], b[j], acc[i][j]);
        }
        __syncthreads();
    }
    #pragma unroll
    for (int i = 0; i < 4; i++) {
        #pragma unroll
        for (int j = 0; j < 4; j++) {
            int col = colBase + tx*4 + j;
            float v = acc[i][j] + (bias ? bias[col] : 0.0f);
            C[(rowBase + ty*4 + i) * Ncols + col] = v;
        }
    }
}

// ---------------- GCN aggregation (gather over CSR) + bias + leaky ----------
__global__ void k_agg(const float* __restrict__ xw, const float* __restrict__ bias,
                      float* __restrict__ out, int F) {
    int n = blockIdx.x;
    int f = threadIdx.x;
    float di = g_dinv[n];
    float acc = di * di * xw[n*F + f];       // self loop
    int s = g_off[n], e = g_off[n+1];
    for (int idx = s; idx < e; idx++)
        acc = fmaf(g_nrm[idx], xw[g_src[idx]*F + f], acc);
    float v = acc + bias[f];
    out[n*F + f] = v > 0.0f ? v : SLOPE * v;
}

// ---------------- S_all = column sum of h2 ----------------------------------
__global__ void k_colsum() {                 // 256 blocks (one per feature)
    int f = blockIdx.x, t = threadIdx.x;
    float s = 0.0f;
    for (int n = t; n < NN; n += 256) s += g_h2[n*256 + f];
    __shared__ float sh[256];
    sh[t] = s; __syncthreads();
    for (int d = 128; d; d >>= 1) { if (t < d) sh[t] += sh[t+d]; __syncthreads(); }
    if (t == 0) g_sall[f] = sh[0];
}

// ---------------- sparse masked softmax attention ----------------------------
// out_i = (e0*S_all + sum_edges (exp(s-m)-e0)*h_j) / (e0*(N-cnt) + sum exp(s-m))
__global__ void k_attn() {
    int warp = (blockIdx.x * blockDim.x + threadIdx.x) >> 5;
    int lane = threadIdx.x & 31;
    if (warp >= NN) return;
    int i = warp;
    float qf[8];
    #pragma unroll
    for (int u = 0; u < 8; u++) qf[u] = g_q[i*256 + lane + 32*u];

    // pass 1: scores + running max (max includes implicit 0s of the mask)
    float m = 0.0f; int cnt = 0;
    for (int w = 0; w < NW; w++) {
        unsigned bits = g_bm[i*NW + w];
        while (bits) {
            int b = __ffs(bits) - 1; bits &= bits - 1;
            int j = w*32 + b;
            float p = 0.0f;
            #pragma unroll
            for (int u = 0; u < 8; u++)
                p = fmaf(qf[u], g_k[j*256 + lane + 32*u], p);
            #pragma unroll
            for (int d = 16; d; d >>= 1) p += __shfl_xor_sync(0xffffffffu, p, d);
            if (lane == 0 && cnt < 128) g_sb[i*128 + cnt] = p;
            m = fmaxf(m, p);
            cnt++;
        }
    }
    float e0 = __expf(-m);
    float Z = 0.0f;
    float acc[8] = {};
    int t2 = 0;
    for (int w = 0; w < NW; w++) {
        unsigned bits = g_bm[i*NW + w];
        while (bits) {
            int b = __ffs(bits) - 1; bits &= bits - 1;
            int j = w*32 + b;
            float s = (t2 < 128) ? g_sb[i*128 + t2] : 0.0f; t2++;
            float wg = __expf(s - m);
            Z += wg;
            float cf = wg - e0;
            #pragma unroll
            for (int u = 0; u < 8; u++)
                acc[u] = fmaf(cf, g_h2[j*256 + lane + 32*u], acc[u]);
        }
    }
    float Zi  = e0 * (float)(NN - cnt) + Z;
    float inv = 1.0f / Zi;
    #pragma unroll
    for (int u = 0; u < 8; u++)
        g_hatt[i*256 + lane + 32*u] = (e0 * g_sall[lane + 32*u] + acc[u]) * inv;
}

// ---------------- residual + layernorm ---------------------------------------
__global__ void k_ln(const float* __restrict__ gamma, const float* __restrict__ beta) {
    int warp = (blockIdx.x * blockDim.x + threadIdx.x) >> 5;
    int lane = threadIdx.x & 31;
    if (warp >= NN) return;
    int n = warp;
    float v0 = g_h3[n*64 + lane]      + g_res[n*64 + lane];
    float v1 = g_h3[n*64 + 32 + lane] + g_res[n*64 + 32 + lane];
    float s = v0 + v1;
    #pragma unroll
    for (int d = 16; d; d >>= 1) s += __shfl_xor_sync(0xffffffffu, s, d);
    float mu = s * (1.0f/64.0f);
    float d0 = v0 - mu, d1 = v1 - mu;
    float q = d0*d0 + d1*d1;
    #pragma unroll
    for (int d = 16; d; d >>= 1) q += __shfl_xor_sync(0xffffffffu, q, d);
    float inv = rsqrtf(q * (1.0f/64.0f) + 1e-5f);
    g_z[n*64 + lane]      = d0 * inv * gamma[lane]      + beta[lane];
    g_z[n*64 + 32 + lane] = d1 * inv * gamma[lane + 32] + beta[lane + 32];
}

// ---------------- max pool over nodes ----------------------------------------
__global__ void k_pool() {                   // 64 blocks, one per feature
    int f = blockIdx.x, t = threadIdx.x;
    float m = -3.4e38f;
    for (int n = t; n < NN; n += 256) m = fmaxf(m, g_z[n*64 + f]);
    __shared__ float sh[256];
    sh[t] = m; __syncthreads();
    for (int d = 128; d; d >>= 1) { if (t < d) sh[t] = fmaxf(sh[t], sh[t+d]); __syncthreads(); }
    if (t == 0) g_pool[f] = sh[0];
}

__global__ void k_final(const float* __restrict__ Wf, const float* __restrict__ bf,
                        float* __restrict__ out) {
    int o = threadIdx.x;
    if (o < 16) {
        float s = bf[o];
        for (int f = 0; f < 64; f++) s = fmaf(g_pool[f], Wf[f*16 + o], s);
        out[o] = s;
    }
}

// ---------------- launch ------------------------------------------------------
extern "C" void kernel_launch(void* const* d_in, const int* in_sizes, int n_in,
                              void* d_out, int out_size) {
    const float* x   = (const float*)d_in[0];
    const void*  ei  =               d_in[1];
    const float* W1  = (const float*)d_in[2];
    const float* b1  = (const float*)d_in[3];
    const float* W2  = (const float*)d_in[4];
    const float* b2  = (const float*)d_in[5];
    const float* W3  = (const float*)d_in[6];
    const float* b3  = (const float*)d_in[7];
    const float* Wk  = (const float*)d_in[8];
    const float* bk  = (const float*)d_in[9];
    const float* Wq  = (const float*)d_in[10];
    const float* bq  = (const float*)d_in[11];
    const float* Wr  = (const float*)d_in[12];
    const float* br  = (const float*)d_in[13];
    const float* lng = (const float*)d_in[14];
    const float* lnb = (const float*)d_in[15];
    const float* Wf  = (const float*)d_in[16];
    const float* bf  = (const float*)d_in[17];
    float* out = (float*)d_out;
    int E = in_sizes[1] / 2;

    void *p;
    cudaGetSymbolAddress(&p, g_xw);   float* xw   = (float*)p;
    cudaGetSymbolAddress(&p, g_h1);   float* h1   = (float*)p;
    cudaGetSymbolAddress(&p, g_h2);   float* h2   = (float*)p;
    cudaGetSymbolAddress(&p, g_q);    float* q    = (float*)p;
    cudaGetSymbolAddress(&p, g_k);    float* k    = (float*)p;
    cudaGetSymbolAddress(&p, g_hatt); float* hatt = (float*)p;
    cudaGetSymbolAddress(&p, g_h3);   float* h3   = (float*)p;
    cudaGetSymbolAddress(&p, g_res);  float* res  = (float*)p;

    int gE = (E + 255) / 256;

    k_zero<<<(NN*NW + 511)/512, 512>>>();
    k_detect<<<1, 256>>>((const long long*)ei, E);
    k_deg<<<gE, 256>>>(ei, E);
    k_dinv<<<(NN + 255)/256, 256>>>();
    k_scan<<<1, 1024>>>();
    k_fill<<<gE, 256>>>(ei, E);
    k_bmset<<<gE, 256>>>(ei, E);

    // GCN1: x@W1 -> agg -> h1 (128)
    k_gemm<<<dim3(2, 128), 256>>>(x, W1, nullptr, xw, 128, 128);
    k_agg<<<NN, 128>>>(xw, b1, h1, 128);
    // GCN2: h1@W2 -> agg -> h2 (256)
    k_gemm<<<dim3(4, 128), 256>>>(h1, W2, nullptr, xw, 128, 256);
    k_agg<<<NN, 256>>>(xw, b2, h2, 256);
    // K, Q
    k_gemm<<<dim3(4, 128), 256>>>(h2, Wk, bk, k, 256, 256);
    k_gemm<<<dim3(4, 128), 256>>>(h2, Wq, bq, q, 256, 256);
    // sparse masked-softmax attention
    k_colsum<<<256, 256>>>();
    k_attn<<<NN/8, 256>>>();
    // GCN3: hatt@W3 -> agg -> h3 (64)
    k_gemm<<<dim3(1, 128), 256>>>(hatt, W3, nullptr, xw, 256, 64);
    k_agg<<<NN, 64>>>(xw, b3, h3, 64);
    // residual
    k_gemm<<<dim3(1, 128), 256>>>(x, Wr, br, res, 128, 64);
    // LN + pool + head
    k_ln<<<NN/8, 256>>>(lng, lnb);
    k_pool<<<64, 256>>>();
    k_final<<<1, 32>>>(Wf, bf, out);
}

// round 2
// speedup vs baseline: 1.3151x; 1.3151x over previous
#include <cuda_runtime.h>
#include <math.h>
#include <stdint.h>

#define NN 8192
#define NW 256
#define EMAX 262144
#define SLOPE 0.01f
#define SCAP 256

// ---------------- scratch ----------------------------------------------------
__device__ float g_xw  [NN*256];
__device__ float g_h1  [NN*128];
__device__ float g_h2  [NN*256];
__device__ float g_q   [NN*256];
__device__ float g_k   [NN*256];
__device__ float g_hatt[NN*256];
__device__ float g_h3  [NN*64];
__device__ float g_res [NN*64];
__device__ float g_dinv[NN];
__device__ int   g_deg [NN];
__device__ int   g_off [NN+1];
__device__ int   g_cur [NN];
__device__ int   g_src [EMAX];
__device__ float g_nrm [EMAX];
__device__ unsigned g_bm[NN*NW];
__device__ float g_sb  [NN*SCAP];
__device__ float g_sall[256];
__device__ unsigned g_poolu[64];
__device__ int   g_is64;

// ---------------- zero + dtype detect ----------------------------------------
__global__ void k_zero(const long long* p, int E) {
    int i = blockIdx.x * blockDim.x + threadIdx.x;
    if (i < NN*NW) g_bm[i] = 0u;
    if (i < NN) { g_deg[i] = 0; g_cur[i] = 0; }
    if (i < 64) g_poolu[i] = 0u;
    if (i < 256) g_sall[i] = 0.0f;
    if (blockIdx.x == 0) {
        __shared__ int bad;
        if (threadIdx.x == 0) bad = 0;
        __syncthreads();
        int step = E / 256; if (step < 1) step = 1;
        if (threadIdx.x < 256) {
            long long pos = (long long)threadIdx.x * step;
            if (pos >= E) pos = E - 1;
            long long v = p[pos];
            if (v < 0 || v >= NN) bad = 1;
        }
        __syncthreads();
        if (threadIdx.x == 0) g_is64 = bad ? 0 : 1;
    }
}

__device__ __forceinline__ void get_edge(const void* ei, int E, int e, int& r, int& c) {
    if (g_is64) {
        const long long* p = (const long long*)ei;
        r = (int)p[e] & (NN-1); c = (int)p[(long long)E + e] & (NN-1);
    } else {
        const int* p = (const int*)ei;
        r = p[e] & (NN-1); c = p[E + e] & (NN-1);
    }
}

// ---------------- graph prep --------------------------------------------------
__global__ void k_degbm(const void* ei, int E) {
    int e = blockIdx.x * blockDim.x + threadIdx.x;
    if (e >= E) return;
    int r, c; get_edge(ei, E, e, r, c);
    atomicAdd(&g_deg[c], 1);
    atomicOr(&g_bm[r*NW + (c >> 5)], 1u << (c & 31));
}

__global__ void k_scan_dinv() {          // 1 block 1024 threads
    __shared__ int sh[1024];
    int t = threadIdx.x;
    int loc[8]; int s = 0;
    #pragma unroll
    for (int i = 0; i < 8; i++) {
        int n = t*8 + i;
        int d = g_deg[n];
        g_dinv[n] = rsqrtf((float)(d + 1));
        loc[i] = d; s += d;
    }
    sh[t] = s; __syncthreads();
    for (int d = 1; d < 1024; d <<= 1) {
        int v = (t >= d) ? sh[t-d] : 0;
        __syncthreads();
        sh[t] += v;
        __syncthreads();
    }
    int excl = sh[t] - s;
    #pragma unroll
    for (int i = 0; i < 8; i++) { g_off[t*8 + i] = excl; excl += loc[i]; }
    if (t == 1023) g_off[NN] = excl;
}

__global__ void k_fill(const void* ei, int E) {
    int e = blockIdx.x * blockDim.x + threadIdx.x;
    if (e >= E) return;
    int r, c; get_edge(ei, E, e, r, c);
    int p = atomicAdd(&g_cur[c], 1);
    int idx = g_off[c] + p;
    g_src[idx] = r;
    g_nrm[idx] = g_dinv[r] * g_dinv[c];
}

// ---------------- tiled GEMM body (double buffered, float4) -------------------
// ACT: 0 none, 1 +bias, 2 +bias+leaky
template<int BM, int BN, int TM, int TN, int ACT>
__device__ __forceinline__ void gemm_body(
    const float* __restrict__ A, const float* __restrict__ W,
    const float* __restrict__ bias, float* __restrict__ C,
    int K, int Ncols, int rowBase, int colBase)
{
    constexpr int BK = 8;
    __shared__ float As[2][BK][BM+4];
    __shared__ float Bs[2][BK][BN+4];
    const int t = threadIdx.x;
    constexpr int TX = BN / TN;
    const int tx = t % TX, ty = t / TX;
    constexpr int A_TH = BM*BK/4;
    constexpr int B_TH = BN*BK/4;
    const int aRow = t >> 1, aK = (t & 1)*4;
    const int bRow = t / (BN/4), bCol = (t % (BN/4))*4;

    float acc[TM][TN] = {};

    if (t < A_TH) {
        float4 v = *(const float4*)&A[(size_t)(rowBase+aRow)*K + aK];
        As[0][aK+0][aRow]=v.x; As[0][aK+1][aRow]=v.y;
        As[0][aK+2][aRow]=v.z; As[0][aK+3][aRow]=v.w;
    }
    if (t < B_TH)
        *(float4*)&Bs[0][bRow][bCol] = *(const float4*)&W[(size_t)bRow*Ncols + colBase + bCol];
    __syncthreads();

    int buf = 0;
    for (int k0 = 0; k0 < K; k0 += BK) {
        float4 an, bn;
        const bool has = (k0 + BK) < K;
        if (has) {
            if (t < A_TH) an = *(const float4*)&A[(size_t)(rowBase+aRow)*K + k0 + BK + aK];
            if (t < B_TH) bn = *(const float4*)&W[(size_t)(k0+BK+bRow)*Ncols + colBase + bCol];
        }
        #pragma unroll
        for (int kk = 0; kk < BK; kk++) {
            float a[TM], b[TN];
            #pragma unroll
            for (int i = 0; i < TM; i += 4)
                *(float4*)&a[i] = *(const float4*)&As[buf][kk][ty*TM + i];
            #pragma unroll
            for (int j = 0; j < TN; j += 4)
                *(float4*)&b[j] = *(const float4*)&Bs[buf][kk][tx*TN + j];
            #pragma unroll
            for (int i = 0; i < TM; i++)
                #pragma unroll
                for (int j = 0; j < TN; j++)
                    acc[i][j] = fmaf(a[i], b[j], acc[i][j]);
        }
        if (has) {
            if (t < A_TH) {
                As[buf^1][aK+0][aRow]=an.x; As[buf^1][aK+1][aRow]=an.y;
                As[buf^1][aK+2][aRow]=an.z; As[buf^1][aK+3][aRow]=an.w;
            }
            if (t < B_TH)
                *(float4*)&Bs[buf^1][bRow][bCol] = bn;
        }
        __syncthreads();
        buf ^= 1;
    }

    #pragma unroll
    for (int i = 0; i < TM; i++) {
        int row = rowBase + ty*TM + i;
        #pragma unroll
        for (int j = 0; j < TN; j += 4) {
            int col = colBase + tx*TN + j;
            float4 v;
            v.x = acc[i][j]; v.y = acc[i][j+1]; v.z = acc[i][j+2]; v.w = acc[i][j+3];
            if (ACT >= 1) {
                float4 b4 = *(const float4*)&bias[col];
                v.x += b4.x; v.y += b4.y; v.z += b4.z; v.w += b4.w;
            }
            if (ACT == 2) {
                v.x = v.x > 0.f ? v.x : SLOPE*v.x;
                v.y = v.y > 0.f ? v.y : SLOPE*v.y;
                v.z = v.z > 0.f ? v.z : SLOPE*v.z;
                v.w = v.w > 0.f ? v.w : SLOPE*v.w;
            }
            *(float4*)&C[(size_t)row*Ncols + col] = v;
        }
    }
}

template<int BM, int BN, int TM, int TN, int ACT>
__global__ void k_gemm(const float* __restrict__ A, const float* __restrict__ W,
                       const float* __restrict__ bias, float* __restrict__ C,
                       int K, int Ncols) {
    gemm_body<BM,BN,TM,TN,ACT>(A, W, bias, C, K, Ncols, blockIdx.y*BM, blockIdx.x*BN);
}

// K and Q GEMMs fused into one launch (grid(4,64))
__global__ void k_gemm_kq(const float* __restrict__ A,
                          const float* __restrict__ W0, const float* __restrict__ W1,
                          const float* __restrict__ b0, const float* __restrict__ b1,
                          float* __restrict__ C0, float* __restrict__ C1) {
    const float* W = (blockIdx.x & 2) ? W1 : W0;
    const float* b = (blockIdx.x & 2) ? b1 : b0;
    float*       C = (blockIdx.x & 2) ? C1 : C0;
    gemm_body<128,128,8,8,1>(A, W, b, C, 256, 256, blockIdx.y*128, (blockIdx.x & 1)*128);
}

// GCN3 xw-GEMM + residual GEMM fused (grid(1,256))
__global__ void k_gemm_pair64(const float* __restrict__ A0, const float* __restrict__ W0,
                              const float* __restrict__ A1, const float* __restrict__ W1,
                              const float* __restrict__ b1,
                              float* __restrict__ C0, float* __restrict__ C1) {
    if (blockIdx.y < 128)
        gemm_body<64,64,4,4,0>(A0, W0, nullptr, C0, 256, 64, blockIdx.y*64, 0);
    else
        gemm_body<64,64,4,4,1>(A1, W1, b1, C1, 128, 64, (blockIdx.y-128)*64, 0);
}

// ---------------- GCN aggregation, float4 ------------------------------------
template<int F, int ACT>
__global__ void k_agg4(const float* __restrict__ xw, const float* __restrict__ bias,
                       float* __restrict__ out) {
    constexpr int TPN = F/4;
    constexpr int NPB = 256/TPN;
    int t = threadIdx.x;
    int n = blockIdx.x*NPB + t/TPN;
    int f4 = (t % TPN)*4;
    float di = g_dinv[n]; float w0 = di*di;
    float4 v = *(const float4*)&xw[(size_t)n*F + f4];
    float4 acc = make_float4(w0*v.x, w0*v.y, w0*v.z, w0*v.w);
    int s = g_off[n], e = g_off[n+1];
    for (int idx = s; idx < e; idx++) {
        int j = g_src[idx]; float wN = g_nrm[idx];
        float4 u = *(const float4*)&xw[(size_t)j*F + f4];
        acc.x = fmaf(wN, u.x, acc.x); acc.y = fmaf(wN, u.y, acc.y);
        acc.z = fmaf(wN, u.z, acc.z); acc.w = fmaf(wN, u.w, acc.w);
    }
    if (ACT) {
        float4 b = *(const float4*)&bias[f4];
        acc.x += b.x; acc.y += b.y; acc.z += b.z; acc.w += b.w;
        acc.x = acc.x > 0.f ? acc.x : SLOPE*acc.x;
        acc.y = acc.y > 0.f ? acc.y : SLOPE*acc.y;
        acc.z = acc.z > 0.f ? acc.z : SLOPE*acc.z;
        acc.w = acc.w > 0.f ? acc.w : SLOPE*acc.w;
    }
    *(float4*)&out[(size_t)n*F + f4] = acc;
}

// ---------------- column sum of h2 (coalesced) --------------------------------
__global__ void k_colsum() {      // grid 256, block 256
    int f = threadIdx.x;
    int r0 = blockIdx.x * 32;
    float s = 0.0f;
    for (int r = 0; r < 32; r++) s += g_h2[(size_t)(r0+r)*256 + f];
    atomicAdd(&g_sall[f], s);
}

// ---------------- sparse masked softmax attention -----------------------------
__global__ void k_attn() {
    int warp = (blockIdx.x * blockDim.x + threadIdx.x) >> 5;
    int lane = threadIdx.x & 31;
    if (warp >= NN) return;
    int i = warp;
    const float4* qp = (const float4*)&g_q[(size_t)i*256];
    float4 q0 = qp[lane*2], q1 = qp[lane*2+1];

    float m = 0.0f; int cnt = 0;
    for (int w = 0; w < NW; w++) {
        unsigned bits = g_bm[i*NW + w];
        while (bits) {
            int b = __ffs(bits) - 1; bits &= bits - 1;
            int j = w*32 + b;
            const float4* kp = (const float4*)&g_k[(size_t)j*256];
            float4 k0 = kp[lane*2], k1 = kp[lane*2+1];
            float p = q0.x*k0.x + q0.y*k0.y + q0.z*k0.z + q0.w*k0.w
                    + q1.x*k1.x + q1.y*k1.y + q1.z*k1.z + q1.w*k1.w;
            #pragma unroll
            for (int d = 16; d; d >>= 1) p += __shfl_xor_sync(0xffffffffu, p, d);
            if (lane == 0 && cnt < SCAP) g_sb[(size_t)i*SCAP + cnt] = p;
            m = fmaxf(m, p);
            cnt++;
        }
    }
    float e0 = __expf(-m);
    float Z = 0.0f;
    float4 a0 = make_float4(0,0,0,0), a1 = make_float4(0,0,0,0);
    int t2 = 0;
    for (int w = 0; w < NW; w++) {
        unsigned bits = g_bm[i*NW + w];
        while (bits) {
            int b = __ffs(bits) - 1; bits &= bits - 1;
            int j = w*32 + b;
            float s = (t2 < SCAP) ? g_sb[(size_t)i*SCAP + t2] : 0.0f; t2++;
            float wg = __expf(s - m);
            Z += wg;
            float cf = wg - e0;
            const float4* hp = (const float4*)&g_h2[(size_t)j*256];
            float4 h0 = hp[lane*2], h1 = hp[lane*2+1];
            a0.x = fmaf(cf, h0.x, a0.x); a0.y = fmaf(cf, h0.y, a0.y);
            a0.z = fmaf(cf, h0.z, a0.z); a0.w = fmaf(cf, h0.w, a0.w);
            a1.x = fmaf(cf, h1.x, a1.x); a1.y = fmaf(cf, h1.y, a1.y);
            a1.z = fmaf(cf, h1.z, a1.z); a1.w = fmaf(cf, h1.w, a1.w);
        }
    }
    float Zi  = e0 * (float)(NN - cnt) + Z;
    float inv = 1.0f / Zi;
    const float4* sp = (const float4*)g_sall;
    float4 s0 = sp[lane*2], s1 = sp[lane*2+1];
    float4 o0, o1;
    o0.x = (e0*s0.x + a0.x)*inv; o0.y = (e0*s0.y + a0.y)*inv;
    o0.z = (e0*s0.z + a0.z)*inv; o0.w = (e0*s0.w + a0.w)*inv;
    o1.x = (e0*s1.x + a1.x)*inv; o1.y = (e0*s1.y + a1.y)*inv;
    o1.z = (e0*s1.z + a1.z)*inv; o1.w = (e0*s1.w + a1.w)*inv;
    float4* op = (float4*)&g_hatt[(size_t)i*256];
    op[lane*2] = o0; op[lane*2+1] = o1;
}

// ---------------- residual + LN + max-pool (fused) ----------------------------
__device__ __forceinline__ unsigned fmap(float f) {
    unsigned b = __float_as_uint(f);
    return (b & 0x80000000u) ? ~b : (b | 0x80000000u);
}

__global__ void k_ln_pool(const float* __restrict__ gamma, const float* __restrict__ beta) {
    __shared__ unsigned sm[64];
    int t = threadIdx.x;
    if (t < 64) sm[t] = 0u;
    __syncthreads();
    int warp = t >> 5, lane = t & 31;
    int n = blockIdx.x*8 + warp;
    float v0 = g_h3[(size_t)n*64 + lane]      + g_res[(size_t)n*64 + lane];
    float v1 = g_h3[(size_t)n*64 + 32 + lane] + g_res[(size_t)n*64 + 32 + lane];
    float s = v0 + v1;
    #pragma unroll
    for (int d = 16; d; d >>= 1) s += __shfl_xor_sync(0xffffffffu, s, d);
    float mu = s * (1.0f/64.0f);
    float d0 = v0 - mu, d1 = v1 - mu;
    float q = d0*d0 + d1*d1;
    #pragma unroll
    for (int d = 16; d; d >>= 1) q += __shfl_xor_sync(0xffffffffu, q, d);
    float inv = rsqrtf(q * (1.0f/64.0f) + 1e-5f);
    float z0 = d0 * inv * gamma[lane]      + beta[lane];
    float z1 = d1 * inv * gamma[lane + 32] + beta[lane + 32];
    atomicMax(&sm[lane],      fmap(z0));
    atomicMax(&sm[lane + 32], fmap(z1));
    __syncthreads();
    if (t < 64) atomicMax(&g_poolu[t], sm[t]);
}

__global__ void k_final(const float* __restrict__ Wf, const float* __restrict__ bf,
                        float* __restrict__ out) {
    __shared__ float pf[64];
    int t = threadIdx.x;
    if (t < 64) {
        unsigned u = g_poolu[t];
        unsigned bits = (u & 0x80000000u) ? (u & 0x7fffffffu) : ~u;
        pf[t] = __uint_as_float(bits);
    }
    __syncthreads();
    if (t < 16) {
        float s = bf[t];
        for (int f = 0; f < 64; f++) s = fmaf(pf[f], Wf[f*16 + t], s);
        out[t] = s;
    }
}

// ---------------- launch ------------------------------------------------------
extern "C" void kernel_launch(void* const* d_in, const int* in_sizes, int n_in,
                              void* d_out, int out_size) {
    const float* x   = (const float*)d_in[0];
    const void*  ei  =               d_in[1];
    const float* W1  = (const float*)d_in[2];
    const float* b1  = (const float*)d_in[3];
    const float* W2  = (const float*)d_in[4];
    const float* b2  = (const float*)d_in[5];
    const float* W3  = (const float*)d_in[6];
    const float* b3  = (const float*)d_in[7];
    const float* Wk  = (const float*)d_in[8];
    const float* bk  = (const float*)d_in[9];
    const float* Wq  = (const float*)d_in[10];
    const float* bq  = (const float*)d_in[11];
    const float* Wr  = (const float*)d_in[12];
    const float* br  = (const float*)d_in[13];
    const float* lng = (const float*)d_in[14];
    const float* lnb = (const float*)d_in[15];
    const float* Wf  = (const float*)d_in[16];
    const float* bf  = (const float*)d_in[17];
    float* out = (float*)d_out;
    int E = in_sizes[1] / 2;

    void *p;
    cudaGetSymbolAddress(&p, g_xw);   float* xw   = (float*)p;
    cudaGetSymbolAddress(&p, g_h1);   float* h1   = (float*)p;
    cudaGetSymbolAddress(&p, g_h2);   float* h2   = (float*)p;
    cudaGetSymbolAddress(&p, g_q);    float* q    = (float*)p;
    cudaGetSymbolAddress(&p, g_k);    float* k    = (float*)p;
    cudaGetSymbolAddress(&p, g_hatt); float* hatt = (float*)p;
    cudaGetSymbolAddress(&p, g_h3);   float* h3   = (float*)p;
    cudaGetSymbolAddress(&p, g_res);  float* res  = (float*)p;

    int gE = (E + 255) / 256;

    k_zero<<<(NN*NW + 511)/512, 512>>>((const long long*)ei, E);
    k_degbm<<<gE, 256>>>(ei, E);
    k_scan_dinv<<<1, 1024>>>();
    k_fill<<<gE, 256>>>(ei, E);

    // GCN1: xw = x@W1 ; h1 = leaky(agg(xw)+b1)
    k_gemm<128,64,8,4,0><<<dim3(2,64), 256>>>(x, W1, nullptr, xw, 128, 128);
    k_agg4<128,1><<<1024, 256>>>(xw, b1, h1);
    // GCN2 (agg-first): xw = agg(h1) ; h2 = leaky(xw@W2 + b2)
    k_agg4<128,0><<<1024, 256>>>(h1, nullptr, xw);
    k_gemm<128,128,8,8,2><<<dim3(2,64), 256>>>(xw, W2, b2, h2, 128, 256);
    // K and Q in one launch
    k_gemm_kq<<<dim3(4,64), 256>>>(h2, Wk, Wq, bk, bq, k, q);
    // attention
    k_colsum<<<256, 256>>>();
    k_attn<<<NN/8, 256>>>();
    // GCN3 xw-GEMM + residual GEMM in one launch
    k_gemm_pair64<<<dim3(1,256), 256>>>(hatt, W3, x, Wr, br, xw, res);
    k_agg4<64,1><<<512, 256>>>(xw, b3, h3);
    // LN + max-pool fused, then head
    k_ln_pool<<<NN/8, 256>>>(lng, lnb);
    k_final<<<1, 64>>>(Wf, bf, out);
}

// round 11
// speedup vs baseline: 1.3965x; 1.0619x over previous
#include <cuda_runtime.h>
#include <math.h>
#include <stdint.h>

#define NN 8192
#define NW 256
#define EMAX 262144
#define SLOPE 0.01f

// ---------------- scratch ----------------------------------------------------
__device__ float g_xw  [NN*256];
__device__ float g_h1  [NN*128];
__device__ float g_h2  [NN*256];
__device__ float g_t   [NN*256];      // t = h2 @ (Wq Wk^T)
__device__ float g_hatt[NN*256];
__device__ float g_h3  [NN*64];
__device__ float g_res [NN*64];
__device__ float g_dinv[NN];
__device__ int   g_deg [NN];
__device__ int   g_off [NN+1];
__device__ int   g_cur [NN];
__device__ int   g_src [EMAX];
__device__ float g_nrm [EMAX];
__device__ unsigned g_bm[NN*NW];
__device__ float g_M   [256*256];
__device__ float g_wu  [256];
__device__ float g_wv  [256];
__device__ float g_c;
__device__ float g_u   [NN];
__device__ float g_v   [NN];
__device__ float g_sall[256];
__device__ unsigned g_poolu[64];
__device__ int   g_is64;

// ---------------- zero + dtype detect ----------------------------------------
__global__ void k_zero(const long long* p, int E) {
    int i = blockIdx.x * blockDim.x + threadIdx.x;
    if (i < NN*NW) g_bm[i] = 0u;
    if (i < NN) { g_deg[i] = 0; g_cur[i] = 0; }
    if (i < 64) g_poolu[i] = 0u;
    if (i < 256) g_sall[i] = 0.0f;
    if (blockIdx.x == 0) {
        __shared__ int bad;
        if (threadIdx.x == 0) bad = 0;
        __syncthreads();
        int step = E / 256; if (step < 1) step = 1;
        if (threadIdx.x < 256) {
            long long pos = (long long)threadIdx.x * step;
            if (pos >= E) pos = E - 1;
            long long v = p[pos];
            if (v < 0 || v >= NN) bad = 1;
        }
        __syncthreads();
        if (threadIdx.x == 0) g_is64 = bad ? 0 : 1;
    }
}

__device__ __forceinline__ void get_edge(const void* ei, int E, int e, int& r, int& c) {
    if (g_is64) {
        const long long* p = (const long long*)ei;
        r = (int)p[e] & (NN-1); c = (int)p[(long long)E + e] & (NN-1);
    } else {
        const int* p = (const int*)ei;
        r = p[e] & (NN-1); c = p[E + e] & (NN-1);
    }
}

// ---------------- graph prep --------------------------------------------------
__global__ void k_degbm(const void* ei, int E) {
    int e = blockIdx.x * blockDim.x + threadIdx.x;
    if (e >= E) return;
    int r, c; get_edge(ei, E, e, r, c);
    atomicAdd(&g_deg[c], 1);
    atomicOr(&g_bm[r*NW + (c >> 5)], 1u << (c & 31));
}

__global__ void k_scan_dinv() {          // 1 block 1024 threads
    __shared__ int sh[1024];
    int t = threadIdx.x;
    int loc[8]; int s = 0;
    #pragma unroll
    for (int i = 0; i < 8; i++) {
        int n = t*8 + i;
        int d = g_deg[n];
        g_dinv[n] = rsqrtf((float)(d + 1));
        loc[i] = d; s += d;
    }
    sh[t] = s; __syncthreads();
    for (int d = 1; d < 1024; d <<= 1) {
        int v = (t >= d) ? sh[t-d] : 0;
        __syncthreads();
        sh[t] += v;
        __syncthreads();
    }
    int excl = sh[t] - s;
    #pragma unroll
    for (int i = 0; i < 8; i++) { g_off[t*8 + i] = excl; excl += loc[i]; }
    if (t == 1023) g_off[NN] = excl;
}

__global__ void k_fill(const void* ei, int E) {
    int e = blockIdx.x * blockDim.x + threadIdx.x;
    if (e >= E) return;
    int r, c; get_edge(ei, E, e, r, c);
    int p = atomicAdd(&g_cur[c], 1);
    int idx = g_off[c] + p;
    g_src[idx] = r;
    g_nrm[idx] = g_dinv[r] * g_dinv[c];
}

// ---------------- prep: M = Wq @ Wk^T, w_u = Wq@bk, w_v = Wk@bq, c = bq.bk ----
// blocks 0..63: M tiles (32x32, NT). blocks 64..95: w_u/w_v. block 96: c.
// smem fills use SCALAR stores (cannot trap on alignment; kernel is tiny).
__global__ void k_prep(const float* __restrict__ Wq, const float* __restrict__ Wk,
                       const float* __restrict__ bq, const float* __restrict__ bk) {
    int blk = blockIdx.x;
    int t = threadIdx.x;
    if (blk < 64) {
        __shared__ float As[32][33];
        __shared__ float Bs[32][33];
        int f0 = (blk / 8) * 32, gcol0 = (blk % 8) * 32;
        int tx = t % 16, ty = t / 16;
        float acc[2][2] = {};
        for (int o0 = 0; o0 < 256; o0 += 32) {
            #pragma unroll
            for (int q2 = 0; q2 < 4; q2++) {
                int idx = t + q2*256;
                int lr = idx >> 5, lc = idx & 31;
                As[lr][lc] = Wq[(f0 + lr)*256 + o0 + lc];
                Bs[lr][lc] = Wk[(gcol0 + lr)*256 + o0 + lc];
            }
            __syncthreads();
            #pragma unroll
            for (int o = 0; o < 32; o++) {
                float a0 = As[ty*2][o],   a1 = As[ty*2+1][o];
                float b0 = Bs[tx*2][o],   b1 = Bs[tx*2+1][o];
                acc[0][0] = fmaf(a0, b0, acc[0][0]);
                acc[0][1] = fmaf(a0, b1, acc[0][1]);
                acc[1][0] = fmaf(a1, b0, acc[1][0]);
                acc[1][1] = fmaf(a1, b1, acc[1][1]);
            }
            __syncthreads();
        }
        #pragma unroll
        for (int i = 0; i < 2; i++)
            #pragma unroll
            for (int j = 0; j < 2; j++)
                g_M[(f0 + ty*2 + i)*256 + gcol0 + tx*2 + j] = acc[i][j];
    } else if (blk < 96) {
        int warp = t >> 5, lane = t & 31;
        int f = (blk - 64)*8 + warp;
        float su = 0.f, sv = 0.f;
        #pragma unroll
        for (int i = 0; i < 8; i++) {
            int o = lane*8 + i;
            su += Wq[f*256 + o] * bk[o];
            sv += Wk[f*256 + o] * bq[o];
        }
        #pragma unroll
        for (int d = 16; d; d >>= 1) {
            su += __shfl_xor_sync(0xffffffffu, su, d);
            sv += __shfl_xor_sync(0xffffffffu, sv, d);
        }
        if (lane == 0) { g_wu[f] = su; g_wv[f] = sv; }
    } else {
        if (t < 32) {
            float s = 0.f;
            #pragma unroll
            for (int i = 0; i < 8; i++) {
                int o = t*8 + i;
                s += bq[o] * bk[o];
            }
            #pragma unroll
            for (int d = 16; d; d >>= 1) s += __shfl_xor_sync(0xffffffffu, s, d);
            if (t == 0) g_c = s;
        }
    }
}

// ---------------- tiled GEMM body (double buffered, float4) -------------------
template<int BM, int BN, int TM, int TN, int ACT>
__device__ __forceinline__ void gemm_body(
    const float* __restrict__ A, const float* __restrict__ W,
    const float* __restrict__ bias, float* __restrict__ C,
    int K, int Ncols, int rowBase, int colBase)
{
    constexpr int BK = 8;
    __shared__ float As[2][BK][BM+4];
    __shared__ float Bs[2][BK][BN+4];
    const int t = threadIdx.x;
    constexpr int TX = BN / TN;
    const int tx = t % TX, ty = t / TX;
    constexpr int A_TH = BM*BK/4;
    constexpr int B_TH = BN*BK/4;
    const int aRow = t >> 1, aK = (t & 1)*4;
    const int bRow = t / (BN/4), bCol = (t % (BN/4))*4;

    float acc[TM][TN] = {};

    if (t < A_TH) {
        float4 v = *(const float4*)&A[(size_t)(rowBase+aRow)*K + aK];
        As[0][aK+0][aRow]=v.x; As[0][aK+1][aRow]=v.y;
        As[0][aK+2][aRow]=v.z; As[0][aK+3][aRow]=v.w;
    }
    if (t < B_TH)
        *(float4*)&Bs[0][bRow][bCol] = *(const float4*)&W[(size_t)bRow*Ncols + colBase + bCol];
    __syncthreads();

    int buf = 0;
    for (int k0 = 0; k0 < K; k0 += BK) {
        float4 an, bn;
        const bool has = (k0 + BK) < K;
        if (has) {
            if (t < A_TH) an = *(const float4*)&A[(size_t)(rowBase+aRow)*K + k0 + BK + aK];
            if (t < B_TH) bn = *(const float4*)&W[(size_t)(k0+BK+bRow)*Ncols + colBase + bCol];
        }
        #pragma unroll
        for (int kk = 0; kk < BK; kk++) {
            float a[TM], b[TN];
            #pragma unroll
            for (int i = 0; i < TM; i += 4)
                *(float4*)&a[i] = *(const float4*)&As[buf][kk][ty*TM + i];
            #pragma unroll
            for (int j = 0; j < TN; j += 4)
                *(float4*)&b[j] = *(const float4*)&Bs[buf][kk][tx*TN + j];
            #pragma unroll
            for (int i = 0; i < TM; i++)
                #pragma unroll
                for (int j = 0; j < TN; j++)
                    acc[i][j] = fmaf(a[i], b[j], acc[i][j]);
        }
        if (has) {
            if (t < A_TH) {
                As[buf^1][aK+0][aRow]=an.x; As[buf^1][aK+1][aRow]=an.y;
                As[buf^1][aK+2][aRow]=an.z; As[buf^1][aK+3][aRow]=an.w;
            }
            if (t < B_TH)
                *(float4*)&Bs[buf^1][bRow][bCol] = bn;
        }
        __syncthreads();
        buf ^= 1;
    }

    #pragma unroll
    for (int i = 0; i < TM; i++) {
        int row = rowBase + ty*TM + i;
        #pragma unroll
        for (int j = 0; j < TN; j += 4) {
            int col = colBase + tx*TN + j;
            float4 v;
            v.x = acc[i][j]; v.y = acc[i][j+1]; v.z = acc[i][j+2]; v.w = acc[i][j+3];
            if (ACT >= 1) {
                float4 b4 = *(const float4*)&bias[col];
                v.x += b4.x; v.y += b4.y; v.z += b4.z; v.w += b4.w;
            }
            if (ACT == 2) {
                v.x = v.x > 0.f ? v.x : SLOPE*v.x;
                v.y = v.y > 0.f ? v.y : SLOPE*v.y;
                v.z = v.z > 0.f ? v.z : SLOPE*v.z;
                v.w = v.w > 0.f ? v.w : SLOPE*v.w;
            }
            *(float4*)&C[(size_t)row*Ncols + col] = v;
        }
    }
}

template<int BM, int BN, int TM, int TN, int ACT>
__global__ void k_gemm(const float* __restrict__ A, const float* __restrict__ W,
                       const float* __restrict__ bias, float* __restrict__ C,
                       int K, int Ncols) {
    gemm_body<BM,BN,TM,TN,ACT>(A, W, bias, C, K, Ncols, blockIdx.y*BM, blockIdx.x*BN);
}

// GCN3 xw-GEMM + residual GEMM fused (grid(1,256))
__global__ void k_gemm_pair64(const float* __restrict__ A0, const float* __restrict__ W0,
                              const float* __restrict__ A1, const float* __restrict__ W1,
                              const float* __restrict__ b1,
                              float* __restrict__ C0, float* __restrict__ C1) {
    if (blockIdx.y < 128)
        gemm_body<64,64,4,4,0>(A0, W0, nullptr, C0, 256, 64, blockIdx.y*64, 0);
    else
        gemm_body<64,64,4,4,1>(A1, W1, b1, C1, 128, 64, (blockIdx.y-128)*64, 0);
}

// ---------------- GCN aggregation, float4 ------------------------------------
template<int F, int ACT>
__global__ void k_agg4(const float* __restrict__ xw, const float* __restrict__ bias,
                       float* __restrict__ out) {
    constexpr int TPN = F/4;
    constexpr int NPB = 256/TPN;
    int t = threadIdx.x;
    int n = blockIdx.x*NPB + t/TPN;
    int f4 = (t % TPN)*4;
    float di = g_dinv[n]; float w0 = di*di;
    float4 v = *(const float4*)&xw[(size_t)n*F + f4];
    float4 acc = make_float4(w0*v.x, w0*v.y, w0*v.z, w0*v.w);
    int s = g_off[n], e = g_off[n+1];
    for (int idx = s; idx < e; idx++) {
        int j = g_src[idx]; float wN = g_nrm[idx];
        float4 u = *(const float4*)&xw[(size_t)j*F + f4];
        acc.x = fmaf(wN, u.x, acc.x); acc.y = fmaf(wN, u.y, acc.y);
        acc.z = fmaf(wN, u.z, acc.z); acc.w = fmaf(wN, u.w, acc.w);
    }
    if (ACT) {
        float4 b = *(const float4*)&bias[f4];
        acc.x += b.x; acc.y += b.y; acc.z += b.z; acc.w += b.w;
        acc.x = acc.x > 0.f ? acc.x : SLOPE*acc.x;
        acc.y = acc.y > 0.f ? acc.y : SLOPE*acc.y;
        acc.z = acc.z > 0.f ? acc.z : SLOPE*acc.z;
        acc.w = acc.w > 0.f ? acc.w : SLOPE*acc.w;
    }
    *(float4*)&out[(size_t)n*F + f4] = acc;
}

// ---------------- u/v per node + column sum of h2 (fused) ---------------------
__global__ void k_uv_colsum() {
    int blk = blockIdx.x;
    int t = threadIdx.x;
    if (blk < 1024) {
        int warp = t >> 5, lane = t & 31;
        int i = blk*8 + warp;
        const float4* hp = (const float4*)&g_h2[(size_t)i*256];
        const float4* up = (const float4*)g_wu;
        const float4* vp = (const float4*)g_wv;
        float su = 0.f, sv = 0.f;
        #pragma unroll
        for (int r = 0; r < 2; r++) {
            float4 h = hp[lane*2+r];
            float4 a = up[lane*2+r];
            float4 b = vp[lane*2+r];
            su += h.x*a.x + h.y*a.y + h.z*a.z + h.w*a.w;
            sv += h.x*b.x + h.y*b.y + h.z*b.z + h.w*b.w;
        }
        #pragma unroll
        for (int d = 16; d; d >>= 1) {
            su += __shfl_xor_sync(0xffffffffu, su, d);
            sv += __shfl_xor_sync(0xffffffffu, sv, d);
        }
        if (lane == 0) { g_u[i] = su; g_v[i] = sv; }
    } else {
        int f = t;
        int r0 = (blk - 1024) * 32;
        float s = 0.0f;
        for (int r = 0; r < 32; r++) s += g_h2[(size_t)(r0+r)*256 + f];
        atomicAdd(&g_sall[f], s);
    }
}

// ---------------- single-pass online-softmax sparse attention -----------------
// s_ij = t_i.h_j + u_i + v_j + c ; softmax over full row with implicit zeros
__global__ void k_attn() {
    int warp = (blockIdx.x * blockDim.x + threadIdx.x) >> 5;
    int lane = threadIdx.x & 31;
    if (warp >= NN) return;
    int i = warp;
    const float4* tp = (const float4*)&g_t[(size_t)i*256];
    float4 t0 = tp[lane*2], t1 = tp[lane*2+1];
    float ui = g_u[i] + g_c;

    float m = 0.0f, Z = 0.0f; int cnt = 0;
    float4 a0 = make_float4(0,0,0,0), a1 = make_float4(0,0,0,0);   // sum wg*h
    float4 s0 = make_float4(0,0,0,0), s1 = make_float4(0,0,0,0);   // sum h (edges)
    for (int w = 0; w < NW; w++) {
        unsigned bits = g_bm[i*NW + w];
        while (bits) {
            int b = __ffs(bits) - 1; bits &= bits - 1;
            int j = w*32 + b;
            const float4* hp = (const float4*)&g_h2[(size_t)j*256];
            float4 h0 = hp[lane*2], h1 = hp[lane*2+1];
            float p = t0.x*h0.x + t0.y*h0.y + t0.z*h0.z + t0.w*h0.w
                    + t1.x*h1.x + t1.y*h1.y + t1.z*h1.z + t1.w*h1.w;
            #pragma unroll
            for (int d = 16; d; d >>= 1) p += __shfl_xor_sync(0xffffffffu, p, d);
            float s = p + ui + g_v[j];
            if (s > m) {
                float sc = __expf(m - s);
                Z *= sc;
                a0.x *= sc; a0.y *= sc; a0.z *= sc; a0.w *= sc;
                a1.x *= sc; a1.y *= sc; a1.z *= sc; a1.w *= sc;
                m = s;
            }
            float wg = __expf(s - m);
            Z += wg;
            a0.x = fmaf(wg, h0.x, a0.x); a0.y = fmaf(wg, h0.y, a0.y);
            a0.z = fmaf(wg, h0.z, a0.z); a0.w = fmaf(wg, h0.w, a0.w);
            a1.x = fmaf(wg, h1.x, a1.x); a1.y = fmaf(wg, h1.y, a1.y);
            a1.z = fmaf(wg, h1.z, a1.z); a1.w = fmaf(wg, h1.w, a1.w);
            s0.x += h0.x; s0.y += h0.y; s0.z += h0.z; s0.w += h0.w;
            s1.x += h1.x; s1.y += h1.y; s1.z += h1.z; s1.w += h1.w;
            cnt++;
        }
    }
    float e0 = __expf(-m);
    float Zt = Z + e0 * (float)(NN - cnt);
    float inv = 1.0f / Zt;
    const float4* sp = (const float4*)g_sall;
    float4 g0 = sp[lane*2], g1 = sp[lane*2+1];
    float4 o0, o1;
    o0.x = (a0.x + e0*(g0.x - s0.x))*inv; o0.y = (a0.y + e0*(g0.y - s0.y))*inv;
    o0.z = (a0.z + e0*(g0.z - s0.z))*inv; o0.w = (a0.w + e0*(g0.w - s0.w))*inv;
    o1.x = (a1.x + e0*(g1.x - s1.x))*inv; o1.y = (a1.y + e0*(g1.y - s1.y))*inv;
    o1.z = (a1.z + e0*(g1.z - s1.z))*inv; o1.w = (a1.w + e0*(g1.w - s1.w))*inv;
    float4* op = (float4*)&g_hatt[(size_t)i*256];
    op[lane*2] = o0; op[lane*2+1] = o1;
}

// ---------------- residual + LN + max-pool (fused) ----------------------------
__device__ __forceinline__ unsigned fmap(float f) {
    unsigned b = __float_as_uint(f);
    return (b & 0x80000000u) ? ~b : (b | 0x80000000u);
}

__global__ void k_ln_pool(const float* __restrict__ gamma, const float* __restrict__ beta) {
    __shared__ unsigned sm[64];
    int t = threadIdx.x;
    if (t < 64) sm[t] = 0u;
    __syncthreads();
    int warp = t >> 5, lane = t & 31;
    int n = blockIdx.x*8 + warp;
    float v0 = g_h3[(size_t)n*64 + lane]      + g_res[(size_t)n*64 + lane];
    float v1 = g_h3[(size_t)n*64 + 32 + lane] + g_res[(size_t)n*64 + 32 + lane];
    float s = v0 + v1;
    #pragma unroll
    for (int d = 16; d; d >>= 1) s += __shfl_xor_sync(0xffffffffu, s, d);
    float mu = s * (1.0f/64.0f);
    float d0 = v0 - mu, d1 = v1 - mu;
    float q = d0*d0 + d1*d1;
    #pragma unroll
    for (int d = 16; d; d >>= 1) q += __shfl_xor_sync(0xffffffffu, q, d);
    float inv = rsqrtf(q * (1.0f/64.0f) + 1e-5f);
    float z0 = d0 * inv * gamma[lane]      + beta[lane];
    float z1 = d1 * inv * gamma[lane + 32] + beta[lane + 32];
    atomicMax(&sm[lane],      fmap(z0));
    atomicMax(&sm[lane + 32], fmap(z1));
    __syncthreads();
    if (t < 64) atomicMax(&g_poolu[t], sm[t]);
}

__global__ void k_final(const float* __restrict__ Wf, const float* __restrict__ bf,
                        float* __restrict__ out) {
    __shared__ float pf[64];
    int t = threadIdx.x;
    if (t < 64) {
        unsigned u = g_poolu[t];
        unsigned bits = (u & 0x80000000u) ? (u & 0x7fffffffu) : ~u;
        pf[t] = __uint_as_float(bits);
    }
    __syncthreads();
    if (t < 16) {
        float s = bf[t];
        for (int f = 0; f < 64; f++) s = fmaf(pf[f], Wf[f*16 + t], s);
        out[t] = s;
    }
}

// ---------------- launch ------------------------------------------------------
extern "C" void kernel_launch(void* const* d_in, const int* in_sizes, int n_in,
                              void* d_out, int out_size) {
    const float* x   = (const float*)d_in[0];
    const void*  ei  =               d_in[1];
    const float* W1  = (const float*)d_in[2];
    const float* b1  = (const float*)d_in[3];
    const float* W2  = (const float*)d_in[4];
    const float* b2  = (const float*)d_in[5];
    const float* W3  = (const float*)d_in[6];
    const float* b3  = (const float*)d_in[7];
    const float* Wk  = (const float*)d_in[8];
    const float* bk  = (const float*)d_in[9];
    const float* Wq  = (const float*)d_in[10];
    const float* bq  = (const float*)d_in[11];
    const float* Wr  = (const float*)d_in[12];
    const float* br  = (const float*)d_in[13];
    const float* lng = (const float*)d_in[14];
    const float* lnb = (const float*)d_in[15];
    const float* Wf  = (const float*)d_in[16];
    const float* bf  = (const float*)d_in[17];
    float* out = (float*)d_out;
    int E = in_sizes[1] / 2;

    void *p;
    cudaGetSymbolAddress(&p, g_xw);   float* xw   = (float*)p;
    cudaGetSymbolAddress(&p, g_h1);   float* h1   = (float*)p;
    cudaGetSymbolAddress(&p, g_h2);   float* h2   = (float*)p;
    cudaGetSymbolAddress(&p, g_t);    float* tt   = (float*)p;
    cudaGetSymbolAddress(&p, g_hatt); float* hatt = (float*)p;
    cudaGetSymbolAddress(&p, g_h3);   float* h3   = (float*)p;
    cudaGetSymbolAddress(&p, g_res);  float* res  = (float*)p;
    cudaGetSymbolAddress(&p, g_M);    float* M    = (float*)p;

    int gE = (E + 255) / 256;

    k_zero<<<(NN*NW + 511)/512, 512>>>((const long long*)ei, E);
    k_degbm<<<gE, 256>>>(ei, E);
    k_scan_dinv<<<1, 1024>>>();
    k_fill<<<gE, 256>>>(ei, E);
    k_prep<<<97, 256>>>(Wq, Wk, bq, bk);

    // GCN1: xw = x@W1 ; h1 = leaky(agg(xw)+b1)
    k_gemm<128,64,8,4,0><<<dim3(2,64), 256>>>(x, W1, nullptr, xw, 128, 128);
    k_agg4<128,1><<<1024, 256>>>(xw, b1, h1);
    // GCN2 (agg-first): xw = agg(h1) ; h2 = leaky(xw@W2 + b2)
    k_agg4<128,0><<<1024, 256>>>(h1, nullptr, xw);
    k_gemm<128,128,8,8,2><<<dim3(2,64), 256>>>(xw, W2, b2, h2, 128, 256);
    // t = h2 @ M
    k_gemm<128,128,8,8,0><<<dim3(2,64), 256>>>(h2, M, nullptr, tt, 256, 256);
    // u, v per node + colsum (fused)
    k_uv_colsum<<<1280, 256>>>();
    // single-pass attention
    k_attn<<<NN/8, 256>>>();
    // GCN3 xw-GEMM + residual GEMM in one launch
    k_gemm_pair64<<<dim3(1,256), 256>>>(hatt, W3, x, Wr, br, xw, res);
    k_agg4<64,1><<<512, 256>>>(xw, b3, h3);
    // LN + max-pool fused, then head
    k_ln_pool<<<NN/8, 256>>>(lng, lnb);
    k_final<<<1, 64>>>(Wf, bf, out);
}